// round 2
// baseline (speedup 1.0000x reference)
#include <cuda_runtime.h>
#include <cuda_bf16.h>
#include <cstdint>

#define D 256
#define NB 16384
#define MARGIN 0.1f
#define EPS 1e-6f

__device__ float  g_inv[NB];
__device__ double g_acc;
__device__ int    g_is64;   // 1 if index arrays are int64, 0 if int32

// ---------------------------------------------------------------------------
// Pass 0: detect index dtype by inspecting raw words of anchor_idx.
// Reads only the first 1 KB — safe for both int32 (1 MB) and int64 (2 MB).
// int64 little-endian with values < 16384 => all odd 32-bit words are zero.
// ---------------------------------------------------------------------------
__global__ void detect_kernel(const unsigned int* __restrict__ raw) {
    if (threadIdx.x == 0) {
        int is64 = 1;
        #pragma unroll 1
        for (int i = 1; i < 256; i += 2) {
            if (raw[i] != 0u) { is64 = 0; break; }
        }
        g_is64 = is64;
        g_acc = 0.0;
    }
}

// ---------------------------------------------------------------------------
// Pass 1: inverse norms, one warp per row.
// ---------------------------------------------------------------------------
__global__ void norms_kernel(const float* __restrict__ pred, int nrows) {
    int warp = (blockIdx.x * blockDim.x + threadIdx.x) >> 5;
    int lane = threadIdx.x & 31;
    int nwarps = (gridDim.x * blockDim.x) >> 5;
    for (int row = warp; row < nrows; row += nwarps) {
        const float4* r = (const float4*)(pred + (size_t)row * D);
        float4 v0 = __ldg(&r[lane]);
        float4 v1 = __ldg(&r[lane + 32]);
        float ss = v0.x * v0.x + v0.y * v0.y + v0.z * v0.z + v0.w * v0.w
                 + v1.x * v1.x + v1.y * v1.y + v1.z * v1.z + v1.w * v1.w;
        #pragma unroll
        for (int o = 16; o > 0; o >>= 1)
            ss += __shfl_xor_sync(0xFFFFFFFFu, ss, o);
        if (lane == 0)
            g_inv[row] = 1.0f / fmaxf(sqrtf(ss), EPS);
    }
}

// ---------------------------------------------------------------------------
// Index fetch honoring detected dtype, clamped for safety.
// ---------------------------------------------------------------------------
__device__ __forceinline__ int fetch_idx(const void* p, int t, int is64) {
    long long v;
    if (is64) v = ((const long long*)p)[t];
    else      v = (long long)((const int*)p)[t];
    int i = (int)v;
    i = i < 0 ? 0 : (i >= NB ? NB - 1 : i);
    return i;
}

// ---------------------------------------------------------------------------
// Pass 2: warp-per-triplet gather + dual dot product + hinge.
// ---------------------------------------------------------------------------
__global__ void __launch_bounds__(256, 8)
triplet_kernel(const float* __restrict__ pred,
               const void* __restrict__ a_idx,
               const void* __restrict__ p_idx,
               const void* __restrict__ n_idx,
               int T) {
    int warp = (blockIdx.x * blockDim.x + threadIdx.x) >> 5;
    int lane = threadIdx.x & 31;
    int wib  = threadIdx.x >> 5;
    int nwarps = (gridDim.x * blockDim.x) >> 5;
    int is64 = g_is64;

    float local = 0.0f;

    for (int t = warp; t < T; t += nwarps) {
        int ia = fetch_idx(a_idx, t, is64);
        int ip = fetch_idx(p_idx, t, is64);
        int in = fetch_idx(n_idx, t, is64);

        const float4* ra = (const float4*)(pred + (size_t)ia * D);
        const float4* rp = (const float4*)(pred + (size_t)ip * D);
        const float4* rn = (const float4*)(pred + (size_t)in * D);

        float4 a0 = __ldg(&ra[lane]);
        float4 a1 = __ldg(&ra[lane + 32]);
        float4 p0 = __ldg(&rp[lane]);
        float4 p1 = __ldg(&rp[lane + 32]);
        float4 n0 = __ldg(&rn[lane]);
        float4 n1 = __ldg(&rn[lane + 32]);

        float dp = fmaf(a0.x, p0.x, fmaf(a0.y, p0.y, fmaf(a0.z, p0.z, a0.w * p0.w)));
        dp = fmaf(a1.x, p1.x, fmaf(a1.y, p1.y, fmaf(a1.z, p1.z, fmaf(a1.w, p1.w, dp))));
        float dn = fmaf(a0.x, n0.x, fmaf(a0.y, n0.y, fmaf(a0.z, n0.z, a0.w * n0.w)));
        dn = fmaf(a1.x, n1.x, fmaf(a1.y, n1.y, fmaf(a1.z, n1.z, fmaf(a1.w, n1.w, dn))));

        #pragma unroll
        for (int o = 16; o > 0; o >>= 1) {
            dp += __shfl_xor_sync(0xFFFFFFFFu, dp, o);
            dn += __shfl_xor_sync(0xFFFFFFFFu, dn, o);
        }

        if (lane == 0) {
            float inva = __ldg(&g_inv[ia]);
            float invp = __ldg(&g_inv[ip]);
            float invn = __ldg(&g_inv[in]);
            float v = dp * inva * invp - dn * inva * invn + MARGIN;
            local += fmaxf(v, 0.0f);
        }
    }

    __shared__ float ssum[8];
    if (lane == 0) ssum[wib] = local;
    __syncthreads();
    if (threadIdx.x == 0) {
        float s = 0.0f;
        #pragma unroll
        for (int i = 0; i < 8; i++) s += ssum[i];
        atomicAdd(&g_acc, (double)s);
    }
}

// ---------------------------------------------------------------------------
// Pass 3: finalize mean.
// ---------------------------------------------------------------------------
__global__ void finalize_kernel(float* __restrict__ out, int T) {
    if (threadIdx.x == 0 && blockIdx.x == 0)
        out[0] = (float)(g_acc / (double)T);
}

extern "C" void kernel_launch(void* const* d_in, const int* in_sizes, int n_in,
                              void* d_out, int out_size) {
    const float* pred  = (const float*)d_in[0];
    const void*  a_idx = d_in[1];
    const void*  p_idx = d_in[2];
    const void*  n_idx = d_in[3];
    float* out = (float*)d_out;

    int nrows = in_sizes[0] / D;    // 16384
    int T     = in_sizes[1];        // 262144

    detect_kernel<<<1, 32>>>((const unsigned int*)a_idx);
    norms_kernel<<<2048, 256>>>(pred, nrows);
    triplet_kernel<<<1184, 256>>>(pred, a_idx, p_idx, n_idx, T);
    finalize_kernel<<<1, 32>>>(out, T);
}

// round 4
// speedup vs baseline: 1.3972x; 1.3972x over previous
#include <cuda_runtime.h>
#include <cuda_fp16.h>
#include <cstdint>

#define D 256
#define NB 16384
#define MARGIN 0.1f
#define EPS 1e-6f

__device__ __half       g_pn[NB * D];   // normalized pred, fp16 (8 MB)
__device__ double       g_acc;
__device__ unsigned int g_count;
__device__ int          g_is64;

// ---------------------------------------------------------------------------
// Kernel 1: dtype detect + zero accumulators + normalize rows into fp16.
// One warp per row.
// ---------------------------------------------------------------------------
__global__ void prep_kernel(const float* __restrict__ pred,
                            const unsigned int* __restrict__ raw_a,
                            int nrows) {
    if (blockIdx.x == 0 && threadIdx.x == 0) {
        int is64 = 1;
        #pragma unroll 1
        for (int i = 1; i < 256; i += 2)
            if (raw_a[i] != 0u) { is64 = 0; break; }
        g_is64 = is64;
        g_acc = 0.0;
        g_count = 0u;
    }

    int warp = (blockIdx.x * blockDim.x + threadIdx.x) >> 5;
    int lane = threadIdx.x & 31;
    if (warp >= nrows) return;

    const float4* r = (const float4*)(pred + (size_t)warp * D);
    float4 v0 = __ldg(&r[lane * 2]);
    float4 v1 = __ldg(&r[lane * 2 + 1]);
    float ss = v0.x * v0.x + v0.y * v0.y + v0.z * v0.z + v0.w * v0.w
             + v1.x * v1.x + v1.y * v1.y + v1.z * v1.z + v1.w * v1.w;
    #pragma unroll
    for (int o = 16; o > 0; o >>= 1)
        ss += __shfl_xor_sync(0xFFFFFFFFu, ss, o);

    float inv = 1.0f / fmaxf(sqrtf(ss), EPS);

    __half h[8];
    h[0] = __float2half(v0.x * inv); h[1] = __float2half(v0.y * inv);
    h[2] = __float2half(v0.z * inv); h[3] = __float2half(v0.w * inv);
    h[4] = __float2half(v1.x * inv); h[5] = __float2half(v1.y * inv);
    h[6] = __float2half(v1.z * inv); h[7] = __float2half(v1.w * inv);

    // 8 halves = 16 bytes: one STG.128 per lane
    *(uint4*)(g_pn + (size_t)warp * D + lane * 8) = *(const uint4*)h;
}

// ---------------------------------------------------------------------------
// Index fetch honoring detected dtype, clamped.
// ---------------------------------------------------------------------------
__device__ __forceinline__ int fetch_idx(const void* p, int t, int is64) {
    int i = is64 ? ((const int*)p)[t << 1]      // low word of little-endian int64
                 : ((const int*)p)[t];
    i = i < 0 ? 0 : (i >= NB ? NB - 1 : i);
    return i;
}

// ---------------------------------------------------------------------------
// Kernel 2: warp-per-triplet gather on fp16 normalized rows + hinge + mean.
// Finalize via last-CTA pattern.
// ---------------------------------------------------------------------------
__global__ void __launch_bounds__(256, 8)
triplet_kernel(const void* __restrict__ a_idx,
               const void* __restrict__ p_idx,
               const void* __restrict__ n_idx,
               float* __restrict__ out,
               int T) {
    int warp = (blockIdx.x * blockDim.x + threadIdx.x) >> 5;
    int lane = threadIdx.x & 31;
    int wib  = threadIdx.x >> 5;
    int nwarps = (gridDim.x * blockDim.x) >> 5;
    int is64 = g_is64;

    float local = 0.0f;

    for (int t = warp; t < T; t += nwarps) {
        int ia = fetch_idx(a_idx, t, is64);
        int ip = fetch_idx(p_idx, t, is64);
        int in = fetch_idx(n_idx, t, is64);

        // each lane: 16 bytes (8 halves) of each 512B row
        uint4 au = __ldg((const uint4*)(g_pn + (size_t)ia * D) + lane);
        uint4 pu = __ldg((const uint4*)(g_pn + (size_t)ip * D) + lane);
        uint4 nu = __ldg((const uint4*)(g_pn + (size_t)in * D) + lane);

        const __half2* ah = (const __half2*)&au;
        const __half2* ph = (const __half2*)&pu;
        const __half2* nh = (const __half2*)&nu;

        float dp = 0.0f, dn = 0.0f;
        #pragma unroll
        for (int j = 0; j < 4; j++) {
            float2 fa = __half22float2(ah[j]);
            float2 fp = __half22float2(ph[j]);
            float2 fn = __half22float2(nh[j]);
            dp = fmaf(fa.x, fp.x, fmaf(fa.y, fp.y, dp));
            dn = fmaf(fa.x, fn.x, fmaf(fa.y, fn.y, dn));
        }

        #pragma unroll
        for (int o = 16; o > 0; o >>= 1) {
            dp += __shfl_xor_sync(0xFFFFFFFFu, dp, o);
            dn += __shfl_xor_sync(0xFFFFFFFFu, dn, o);
        }

        if (lane == 0)
            local += fmaxf(dp - dn + MARGIN, 0.0f);
    }

    __shared__ float ssum[8];
    __shared__ bool  is_last;
    if (lane == 0) ssum[wib] = local;
    __syncthreads();
    if (threadIdx.x == 0) {
        float s = 0.0f;
        #pragma unroll
        for (int i = 0; i < 8; i++) s += ssum[i];
        atomicAdd(&g_acc, (double)s);
        __threadfence();
        unsigned int n = atomicAdd(&g_count, 1u);
        is_last = (n == gridDim.x - 1);
    }
    __syncthreads();
    if (is_last && threadIdx.x == 0) {
        __threadfence();
        out[0] = (float)(*(volatile double*)&g_acc / (double)T);
        g_count = 0u;   // reset for next replay
    }
}

extern "C" void kernel_launch(void* const* d_in, const int* in_sizes, int n_in,
                              void* d_out, int out_size) {
    const float* pred  = (const float*)d_in[0];
    const void*  a_idx = d_in[1];
    const void*  p_idx = d_in[2];
    const void*  n_idx = d_in[3];
    float* out = (float*)d_out;

    int nrows = in_sizes[0] / D;    // 16384
    int T     = in_sizes[1];        // 262144

    prep_kernel<<<2048, 256>>>(pred, (const unsigned int*)a_idx, nrows);
    triplet_kernel<<<1184, 256>>>(a_idx, p_idx, n_idx, out, T);
}